// round 1
// baseline (speedup 1.0000x reference)
#include <cuda_runtime.h>
#include <math.h>

#define BB   32
#define NIN  1024
#define DIN  512
#define NOUT 32
#define DCAP 64
#define FANOUT 2048   // NOUT*DCAP

// ---- scratch (device globals; no allocation) ----
__device__ float d_g0[BB*DIN];          // iter-0 mean of u over n      (64 KB)
__device__ float d_g [BB*NOUT*DIN];     // g[b,o,k]                     (2 MB)
__device__ float d_c [BB*NOUT*DIN];     // c[b,o,k] = W_o @ vjn         (2 MB)
__device__ float d_vj[BB*NOUT*DCAP];    // vj[b,o,d]                    (256 KB)
__device__ float d_wv[BB*NOUT*NIN];     // softmax weights Wv[b,o,n]    (4 MB)
__device__ float d_inv[1];              // 1 / global L2 norm of vj

// ---------------------------------------------------------------------------
// g0[b,k] = (1/32) * sum_n u[b,n,k]     (iter-0 uniform softmax folded in)
__global__ void g0_kernel(const float* __restrict__ u) {
    int b = blockIdx.x, kt = blockIdx.y;
    int k = kt * 128 + threadIdx.x;
    const float* up = u + (size_t)b * NIN * DIN + k;
    float acc = 0.f;
#pragma unroll 8
    for (int n = 0; n < NIN; n++) acc += up[(size_t)n * DIN];
    d_g0[b * DIN + k] = acc * (1.0f / 32.0f);
}

// vj0[b, j] = sum_k g0[b,k] * W[k,j]   (j = o*64+d; 8 b per block)
__global__ void vj0_kernel(const float* __restrict__ W) {
    __shared__ float g0s[8 * DIN];
    int ct = blockIdx.x, bq = blockIdx.y, tid = threadIdx.x;
    for (int i = 0; i < 16; i++) {
        int e = i * 256 + tid;                 // 4096 elems
        int q = e >> 9, k = e & 511;
        g0s[e] = d_g0[(bq * 8 + q) * DIN + k];
        (void)q; (void)k;
    }
    __syncthreads();
    int j = ct * 256 + tid;
    float acc[8] = {};
#pragma unroll 4
    for (int k = 0; k < DIN; k++) {
        float w = W[(size_t)k * FANOUT + j];
#pragma unroll
        for (int q = 0; q < 8; q++) acc[q] += w * g0s[q * DIN + k];
    }
#pragma unroll
    for (int q = 0; q < 8; q++) d_vj[(bq * 8 + q) * FANOUT + j] = acc[q];
}

// ---------------------------------------------------------------------------
// global L2 norm of vj (axis=None in reference!) -> store reciprocal
__global__ void norm_kernel() {
    __shared__ float red[512];
    int tid = threadIdx.x;
    float s = 0.f;
    for (int i = tid; i < BB * NOUT * DCAP; i += 512) {
        float v = d_vj[i]; s += v * v;
    }
    red[tid] = s; __syncthreads();
    for (int st = 256; st > 0; st >>= 1) {
        if (tid < st) red[tid] += red[tid + st];
        __syncthreads();
    }
    if (tid == 0) d_inv[0] = 1.0f / sqrtf(fmaxf(red[0], 1e-12f));
}

// c[b,o,k] = sum_d W[k, o*64+d] * vj[b,o,d] * inv_norm
__global__ void c_kernel(const float* __restrict__ W) {
    __shared__ float vjs[BB * DCAP];   // [b][d]
    int o = blockIdx.x, kt = blockIdx.y, tid = threadIdx.x;
    float inv = d_inv[0];
    for (int i = 0; i < 16; i++) {
        int e = i * 128 + tid;                 // 2048 elems
        int bb = e >> 6, d = e & 63;
        vjs[e] = d_vj[(bb * NOUT + o) * DCAP + d] * inv;
    }
    __syncthreads();
    int kg = kt * 128 + tid;
    const float* wp = W + (size_t)kg * FANOUT + o * DCAP;
    float wrow[64];
#pragma unroll
    for (int d = 0; d < 64; d++) wrow[d] = wp[d];
    for (int bb = 0; bb < BB; bb++) {
        float acc = 0.f;
#pragma unroll
        for (int d = 0; d < 64; d++) acc += wrow[d] * vjs[bb * 64 + d];
        d_c[(bb * NOUT + o) * DIN + kg] = acc;
    }
}

// ---------------------------------------------------------------------------
// fused: b[b,o,n] = sum_k u[b,n,k]*c[b,o,k]; softmax over o; write Wv[b,o,n]
// tile 128n x 32o per block, 128 threads, 8n x 4o per thread
__global__ void route_kernel(const float* __restrict__ u) {
    __shared__ float us[128 * 33];
    __shared__ float cs[32 * 33];
    __shared__ float ts[128 * 33];
    int b = blockIdx.x, n0 = blockIdx.y * 128, tid = threadIdx.x;
    int to = tid & 7, tn = tid >> 3;
    float acc[8][4] = {};
    const float* ub = u + ((size_t)b * NIN + n0) * DIN;
    const float* cb = d_c + b * NOUT * DIN;
    for (int k0 = 0; k0 < DIN; k0 += 32) {
        __syncthreads();
        for (int i = 0; i < 32; i++) {
            int e = i * 128 + tid; int n = e >> 5, kk = e & 31;
            us[n * 33 + kk] = ub[(size_t)n * DIN + k0 + kk];
        }
        for (int i = 0; i < 8; i++) {
            int e = i * 128 + tid; int oo = e >> 5, kk = e & 31;
            cs[oo * 33 + kk] = cb[oo * DIN + k0 + kk];
        }
        __syncthreads();
#pragma unroll
        for (int kk = 0; kk < 32; kk++) {
            float a[8], bv[4];
#pragma unroll
            for (int i = 0; i < 8; i++) a[i] = us[(tn * 8 + i) * 33 + kk];
#pragma unroll
            for (int j = 0; j < 4; j++) bv[j] = cs[(to * 4 + j) * 33 + kk];
#pragma unroll
            for (int i = 0; i < 8; i++)
#pragma unroll
                for (int j = 0; j < 4; j++) acc[i][j] += a[i] * bv[j];
        }
    }
    __syncthreads();
#pragma unroll
    for (int i = 0; i < 8; i++)
#pragma unroll
        for (int j = 0; j < 4; j++)
            ts[(tn * 8 + i) * 33 + to * 4 + j] = acc[i][j];
    __syncthreads();
    {   // softmax over the 32 o values; one n per thread
        int n = tid;
        float m = -1e30f;
#pragma unroll
        for (int o = 0; o < 32; o++) m = fmaxf(m, ts[n * 33 + o]);
        float ex[32], s = 0.f;
#pragma unroll
        for (int o = 0; o < 32; o++) { ex[o] = expf(ts[n * 33 + o] - m); s += ex[o]; }
        float rs = 1.0f / s;
#pragma unroll
        for (int o = 0; o < 32; o++) ts[n * 33 + o] = ex[o] * rs;
    }
    __syncthreads();
    for (int o = 0; o < 32; o++)
        d_wv[(b * NOUT + o) * NIN + n0 + tid] = ts[tid * 33 + o];
}

// ---------------------------------------------------------------------------
// g[b,o,k] = sum_n Wv[b,o,n] * u[b,n,k]   tile 32o x 128k, 128 threads
__global__ void g_kernel(const float* __restrict__ u) {
    __shared__ float wvs[32 * 33];
    __shared__ float us[32 * 132];
    int b = blockIdx.x, kt = blockIdx.y, tid = threadIdx.x;
    int tk = tid & 15, to = tid >> 4;      // k = tk*8.., o = to*4..
    float acc[4][8] = {};
    const float* ub = u + (size_t)b * NIN * DIN + kt * 128;
    const float* wb = d_wv + b * NOUT * NIN;
    for (int n0 = 0; n0 < NIN; n0 += 32) {
        __syncthreads();
        for (int i = 0; i < 8; i++) {
            int e = i * 128 + tid; int oo = e >> 5, nn = e & 31;
            wvs[oo * 33 + nn] = wb[oo * NIN + n0 + nn];
        }
        for (int i = 0; i < 32; i++) {
            int e = i * 128 + tid; int nn = e >> 7, kk = e & 127;
            us[nn * 132 + kk] = ub[(size_t)(n0 + nn) * DIN + kk];
        }
        __syncthreads();
#pragma unroll
        for (int nn = 0; nn < 32; nn++) {
            float4 a0 = *reinterpret_cast<const float4*>(&us[nn * 132 + tk * 8]);
            float4 a1 = *reinterpret_cast<const float4*>(&us[nn * 132 + tk * 8 + 4]);
            float wr[4];
#pragma unroll
            for (int j = 0; j < 4; j++) wr[j] = wvs[(to * 4 + j) * 33 + nn];
#pragma unroll
            for (int j = 0; j < 4; j++) {
                acc[j][0] += wr[j] * a0.x; acc[j][1] += wr[j] * a0.y;
                acc[j][2] += wr[j] * a0.z; acc[j][3] += wr[j] * a0.w;
                acc[j][4] += wr[j] * a1.x; acc[j][5] += wr[j] * a1.y;
                acc[j][6] += wr[j] * a1.z; acc[j][7] += wr[j] * a1.w;
            }
        }
    }
#pragma unroll
    for (int j = 0; j < 4; j++)
#pragma unroll
        for (int q = 0; q < 8; q++)
            d_g[(b * NOUT + to * 4 + j) * DIN + kt * 128 + tk * 8 + q] = acc[j][q];
}

// vj[b,o,d] = sum_k g[b,o,k] * W[k, o*64+d]   (block: one o, 16 b)
__global__ void vj_kernel(const float* __restrict__ W) {
    __shared__ float gs[16 * DIN];   // 32 KB
    int o = blockIdx.x, bh = blockIdx.y, tid = threadIdx.x;
    for (int i = 0; i < 32; i++) {
        int e = i * 256 + tid;                 // 8192 elems
        int bl = e >> 9, k = e & 511;
        gs[e] = d_g[((bh * 16 + bl) * NOUT + o) * DIN + k];
        (void)bl; (void)k;
    }
    __syncthreads();
    int d = tid & 63, bg = tid >> 6;           // bg 0..3 -> 4 b each
    float acc[4] = {};
    const float* wp = W + o * DCAP + d;
#pragma unroll 4
    for (int k = 0; k < DIN; k++) {
        float w = wp[(size_t)k * FANOUT];
#pragma unroll
        for (int j = 0; j < 4; j++) acc[j] += w * gs[(bg * 4 + j) * DIN + k];
    }
#pragma unroll
    for (int j = 0; j < 4; j++)
        d_vj[((bh * 16 + bg * 4 + j) * NOUT + o) * DCAP + d] = acc[j];
}

// ---------------------------------------------------------------------------
// squash(vj, axis=-1): s = sum_d v^2 + 1e-7; out = v * sqrt(s)/(0.5+s)
__global__ void squash_kernel(float* __restrict__ out) {
    int bo = blockIdx.x, d = threadIdx.x;
    float v = d_vj[bo * DCAP + d];
    float sq = v * v;
#pragma unroll
    for (int off = 16; off > 0; off >>= 1)
        sq += __shfl_xor_sync(0xffffffffu, sq, off);
    __shared__ float part[2];
    if ((d & 31) == 0) part[d >> 5] = sq;
    __syncthreads();
    float s = part[0] + part[1] + 1e-7f;
    float scale = sqrtf(s) / (0.5f + s);
    out[bo * DCAP + d] = v * scale;
}

// ---------------------------------------------------------------------------
extern "C" void kernel_launch(void* const* d_in, const int* in_sizes, int n_in,
                              void* d_out, int out_size) {
    const float* u = (const float*)d_in[0];   // [32,1024,512]
    const float* W = (const float*)d_in[1];   // [512,2048]
    float* out = (float*)d_out;               // [32,32,64]

    // iter 0: uniform softmax -> column mean of u, project through W
    g0_kernel<<<dim3(32, 4), 128>>>(u);
    vj0_kernel<<<dim3(8, 4), 256>>>(W);

    for (int it = 0; it < 2; it++) {
        norm_kernel<<<1, 512>>>();                 // global L2 of vj
        c_kernel<<<dim3(32, 4), 128>>>(W);         // c = W_o @ vjn
        route_kernel<<<dim3(32, 8), 128>>>(u);     // b = u.c, softmax -> Wv
        g_kernel<<<dim3(32, 4), 128>>>(u);         // g = Wv @ u
        vj_kernel<<<dim3(32, 2), 256>>>(W);        // vj = g @ W_o
    }

    squash_kernel<<<1024, 64>>>(out);
}

// round 2
// speedup vs baseline: 1.1767x; 1.1767x over previous
#include <cuda_runtime.h>
#include <math.h>

#define BB   32
#define NIN  1024
#define DIN  512
#define NOUT 32
#define DCAP 64
#define FANOUT 2048   // NOUT*DCAP

// ---- scratch (device globals; no allocation) ----
__device__ float d_g0p[8*BB*DIN];       // n-split partial sums for g0   (512 KB)
__device__ float d_g [BB*NOUT*DIN];     // g[b,o,k]                      (2 MB)
__device__ float d_c [BB*NOUT*DIN];     // c[b,o,k] = W_o @ vjn          (2 MB)
__device__ float d_vj[BB*NOUT*DCAP];    // vj[b,o,d]                     (256 KB)
__device__ float d_wv[BB*NOUT*NIN];     // softmax weights Wv[b,o,n]     (4 MB)
__device__ float d_inv[1];              // 1 / global L2 norm of vj

// ---------------------------------------------------------------------------
// partial[nt][b][k] = sum over 128 n of u[b,n,k]   (grid 32 x 4 x 8)
__global__ void g0_kernel(const float* __restrict__ u) {
    int b = blockIdx.x, kt = blockIdx.y, nt = blockIdx.z;
    int k = kt * 128 + threadIdx.x;
    const float* up = u + ((size_t)b * NIN + nt * 128) * DIN + k;
    float acc = 0.f;
#pragma unroll 8
    for (int n = 0; n < 128; n++) acc += up[(size_t)n * DIN];
    d_g0p[(nt * BB + b) * DIN + k] = acc;
}

// vj0[b,j] = sum_k g0[b,k] * W[k,j]; g0 = (1/32)*sum of 8 partials
// grid (8 jt x 8 bt of 4b), 256 threads
__global__ void vj0_kernel(const float* __restrict__ W) {
    __shared__ float g0s[4 * DIN];     // 8 KB
    int jt = blockIdx.x, bt = blockIdx.y, tid = threadIdx.x;
    // fill: 2048 elems, summing 8 partials, scaled by 1/32
    for (int i = 0; i < 8; i++) {
        int e = i * 256 + tid;
        int bl = e >> 9, k = e & 511;
        float s = 0.f;
#pragma unroll
        for (int nt = 0; nt < 8; nt++)
            s += d_g0p[(nt * BB + bt * 4 + bl) * DIN + k];
        g0s[e] = s * (1.0f / 32.0f);
    }
    __syncthreads();
    int j = jt * 256 + tid;
    float acc[4] = {};
#pragma unroll 8
    for (int k = 0; k < DIN; k++) {
        float w = W[(size_t)k * FANOUT + j];
#pragma unroll
        for (int q = 0; q < 4; q++) acc[q] += w * g0s[q * DIN + k];
    }
#pragma unroll
    for (int q = 0; q < 4; q++) d_vj[(bt * 4 + q) * FANOUT + j] = acc[q];
}

// ---------------------------------------------------------------------------
// global L2 norm of vj (axis=None in reference) -> store reciprocal
__global__ void norm_kernel() {
    __shared__ float red[32];
    int tid = threadIdx.x;
    const float4* v4 = (const float4*)d_vj;
    float s = 0.f;
#pragma unroll
    for (int i = 0; i < 16; i++) {
        float4 v = v4[i * 1024 + tid];
        s += v.x * v.x + v.y * v.y + v.z * v.z + v.w * v.w;
    }
#pragma unroll
    for (int off = 16; off > 0; off >>= 1) s += __shfl_xor_sync(~0u, s, off);
    if ((tid & 31) == 0) red[tid >> 5] = s;
    __syncthreads();
    if (tid < 32) {
        float t = red[tid];
#pragma unroll
        for (int off = 16; off > 0; off >>= 1) t += __shfl_xor_sync(~0u, t, off);
        if (tid == 0) d_inv[0] = 1.0f / sqrtf(fmaxf(t, 1e-12f));
    }
}

// c[b,o,k] = sum_d W[k, o*64+d] * vj[b,o,d] * inv_norm
// grid (32 o x 4 kt of 128), 128 threads (thread = k)
__global__ void c_kernel(const float* __restrict__ W) {
    __shared__ float vt[64 * 36];      // [d][bb] pad 36
    __shared__ float ws[128 * 65];     // [kl][d] pad 65
    int o = blockIdx.x, kt = blockIdx.y, tid = threadIdx.x;
    float inv = d_inv[0];
    // fill vt (transposed, scaled)
    for (int i = 0; i < 16; i++) {
        int e = i * 128 + tid;
        int bb = e >> 6, d = e & 63;
        vt[d * 36 + bb] = d_vj[(bb * NOUT + o) * DCAP + d] * inv;
    }
    // fill ws: W[k0+kl, o*64 + d]  (coalesced float4 loads)
    {
        const float* wp = W + (size_t)(kt * 128) * FANOUT + o * DCAP;
        for (int i = 0; i < 16; i++) {
            int e4 = i * 128 + tid;
            int kl = e4 >> 4, dq = e4 & 15;
            float4 v = *(const float4*)&wp[(size_t)kl * FANOUT + dq * 4];
            ws[kl * 65 + dq * 4 + 0] = v.x;
            ws[kl * 65 + dq * 4 + 1] = v.y;
            ws[kl * 65 + dq * 4 + 2] = v.z;
            ws[kl * 65 + dq * 4 + 3] = v.w;
        }
    }
    __syncthreads();
    float acc[32] = {};
#pragma unroll 4
    for (int d = 0; d < 64; d++) {
        float w = ws[tid * 65 + d];
#pragma unroll
        for (int bq = 0; bq < 8; bq++) {
            float4 v = *(const float4*)&vt[d * 36 + bq * 4];
            acc[bq * 4 + 0] += w * v.x;
            acc[bq * 4 + 1] += w * v.y;
            acc[bq * 4 + 2] += w * v.z;
            acc[bq * 4 + 3] += w * v.w;
        }
    }
    int kg = kt * 128 + tid;
#pragma unroll
    for (int bb = 0; bb < 32; bb++)
        d_c[(bb * NOUT + o) * DIN + kg] = acc[bb];
}

// ---------------------------------------------------------------------------
// fused: b[b,o,n] = sum_k u[b,n,k]*c[b,o,k]; softmax over o; write Wv[b,o,n]
// tile 128n x 32o, 256 threads, 4n x 4o per thread, k-chunk 32
__global__ void route_kernel(const float* __restrict__ u) {
    __shared__ float sa[32 * 132];     // us_t [kk][n] during loop; ts [n][33] after
    __shared__ float sc[32 * 36];      // cs_t [kk][o]
    int b = blockIdx.x, n0 = blockIdx.y * 128, tid = threadIdx.x;
    int tn = tid & 31, to = tid >> 5;
    float acc[4][4] = {};
    const float* ub = u + ((size_t)b * NIN + n0) * DIN;
    const float* cb = d_c + b * NOUT * DIN;
    for (int k0 = 0; k0 < DIN; k0 += 32) {
        __syncthreads();
#pragma unroll
        for (int i = 0; i < 16; i++) {
            int e = i * 256 + tid; int n = e >> 5, kk = e & 31;
            sa[kk * 132 + n] = ub[(size_t)n * DIN + k0 + kk];
        }
#pragma unroll
        for (int i = 0; i < 4; i++) {
            int e = i * 256 + tid; int o = e >> 5, kk = e & 31;
            sc[kk * 36 + o] = cb[o * DIN + k0 + kk];
        }
        __syncthreads();
#pragma unroll
        for (int kk = 0; kk < 32; kk++) {
            float4 av = *(const float4*)&sa[kk * 132 + tn * 4];
            float4 bv = *(const float4*)&sc[kk * 36 + to * 4];
            acc[0][0] += av.x * bv.x; acc[0][1] += av.x * bv.y;
            acc[0][2] += av.x * bv.z; acc[0][3] += av.x * bv.w;
            acc[1][0] += av.y * bv.x; acc[1][1] += av.y * bv.y;
            acc[1][2] += av.y * bv.z; acc[1][3] += av.y * bv.w;
            acc[2][0] += av.z * bv.x; acc[2][1] += av.z * bv.y;
            acc[2][2] += av.z * bv.z; acc[2][3] += av.z * bv.w;
            acc[3][0] += av.w * bv.x; acc[3][1] += av.w * bv.y;
            acc[3][2] += av.w * bv.z; acc[3][3] += av.w * bv.w;
        }
    }
    __syncthreads();
    // spill b-tile to ts[n][o] (stride 33) in sa
#pragma unroll
    for (int i = 0; i < 4; i++)
#pragma unroll
        for (int j = 0; j < 4; j++)
            sa[(tn * 4 + i) * 33 + to * 4 + j] = acc[i][j];
    __syncthreads();
    if (tid < 128) {   // softmax over 32 o for n=tid
        int n = tid;
        float m = -1e30f;
#pragma unroll
        for (int o = 0; o < 32; o++) m = fmaxf(m, sa[n * 33 + o]);
        float ex[32], s = 0.f;
#pragma unroll
        for (int o = 0; o < 32; o++) { ex[o] = expf(sa[n * 33 + o] - m); s += ex[o]; }
        float rs = 1.0f / s;
#pragma unroll
        for (int o = 0; o < 32; o++) sa[n * 33 + o] = ex[o] * rs;
    }
    __syncthreads();
#pragma unroll
    for (int i = 0; i < 16; i++) {
        int e = i * 256 + tid; int o = e >> 7, n = e & 127;
        d_wv[(b * NOUT + o) * NIN + n0 + n] = sa[n * 33 + o];
    }
}

// ---------------------------------------------------------------------------
// g[b,o,k] = sum_n Wv[b,o,n] * u[b,n,k]
// tile 32o x 128k, 256 threads, 4o x 4k per thread, n-chunk 32
__global__ void g_kernel(const float* __restrict__ u) {
    __shared__ float su[32 * 132];     // [nn][k] pad 132
    __shared__ float sw[32 * 36];      // [nn][o] pad 36
    int b = blockIdx.x, k0 = blockIdx.y * 128, tid = threadIdx.x;
    int tk = tid & 31, to = tid >> 5;
    float acc[4][4] = {};              // [o][k]
    const float* ub = u + (size_t)b * NIN * DIN + k0;
    const float* wb = d_wv + b * NOUT * NIN;
    for (int n0 = 0; n0 < NIN; n0 += 32) {
        __syncthreads();
#pragma unroll
        for (int i = 0; i < 4; i++) {
            int e4 = i * 256 + tid; int nn = e4 >> 5, kq = e4 & 31;
            float4 v = *(const float4*)&ub[(size_t)(n0 + nn) * DIN + kq * 4];
            *(float4*)&su[nn * 132 + kq * 4] = v;
        }
#pragma unroll
        for (int i = 0; i < 4; i++) {
            int e = i * 256 + tid; int nn = e & 31, o = e >> 5;
            sw[nn * 36 + o] = wb[o * NIN + n0 + nn];
        }
        __syncthreads();
#pragma unroll
        for (int nn = 0; nn < 32; nn++) {
            float4 av = *(const float4*)&su[nn * 132 + tk * 4];
            float4 wv = *(const float4*)&sw[nn * 36 + to * 4];
            acc[0][0] += wv.x * av.x; acc[0][1] += wv.x * av.y;
            acc[0][2] += wv.x * av.z; acc[0][3] += wv.x * av.w;
            acc[1][0] += wv.y * av.x; acc[1][1] += wv.y * av.y;
            acc[1][2] += wv.y * av.z; acc[1][3] += wv.y * av.w;
            acc[2][0] += wv.z * av.x; acc[2][1] += wv.z * av.y;
            acc[2][2] += wv.z * av.z; acc[2][3] += wv.z * av.w;
            acc[3][0] += wv.w * av.x; acc[3][1] += wv.w * av.y;
            acc[3][2] += wv.w * av.z; acc[3][3] += wv.w * av.w;
        }
    }
#pragma unroll
    for (int j = 0; j < 4; j++) {
        float4 v = make_float4(acc[j][0], acc[j][1], acc[j][2], acc[j][3]);
        *(float4*)&d_g[(b * NOUT + to * 4 + j) * DIN + k0 + tk * 4] = v;
    }
}

// vj[b,o,d] = sum_k g[b,o,k] * W[k, o*64+d]
// grid (32 o x 4 bh of 8b), 256 threads = 32 d2(float2) x 8 b
__global__ void vj_kernel(const float* __restrict__ W) {
    __shared__ float gs[8 * DIN];      // 16 KB
    int o = blockIdx.x, bh = blockIdx.y, tid = threadIdx.x;
    for (int i = 0; i < 16; i++) {
        int e = i * 256 + tid;
        int bl = e >> 9, k = e & 511;
        gs[e] = d_g[((bh * 8 + bl) * NOUT + o) * DIN + k];
        (void)bl; (void)k;
    }
    __syncthreads();
    int d2 = tid & 31, bg = tid >> 5;
    const float* wp = W + o * DCAP + d2 * 2;
    const float* gp = gs + bg * DIN;
    float a0 = 0.f, a1 = 0.f;
#pragma unroll 8
    for (int k = 0; k < DIN; k++) {
        float2 w = *(const float2*)&wp[(size_t)k * FANOUT];
        float g = gp[k];
        a0 += w.x * g;
        a1 += w.y * g;
    }
    float2* outp = (float2*)&d_vj[((bh * 8 + bg) * NOUT + o) * DCAP + d2 * 2];
    *outp = make_float2(a0, a1);
}

// ---------------------------------------------------------------------------
// squash(vj, axis=-1): s = sum_d v^2 + 1e-7; out = v * sqrt(s)/(0.5+s)
__global__ void squash_kernel(float* __restrict__ out) {
    int bo = blockIdx.x, d = threadIdx.x;
    float v = d_vj[bo * DCAP + d];
    float sq = v * v;
#pragma unroll
    for (int off = 16; off > 0; off >>= 1)
        sq += __shfl_xor_sync(0xffffffffu, sq, off);
    __shared__ float part[2];
    if ((d & 31) == 0) part[d >> 5] = sq;
    __syncthreads();
    float s = part[0] + part[1] + 1e-7f;
    float scale = sqrtf(s) / (0.5f + s);
    out[bo * DCAP + d] = v * scale;
}

// ---------------------------------------------------------------------------
extern "C" void kernel_launch(void* const* d_in, const int* in_sizes, int n_in,
                              void* d_out, int out_size) {
    const float* u = (const float*)d_in[0];   // [32,1024,512]
    const float* W = (const float*)d_in[1];   // [512,2048]
    float* out = (float*)d_out;               // [32,32,64]

    // iter 0: uniform softmax -> column mean of u, project through W
    g0_kernel<<<dim3(32, 4, 8), 128>>>(u);
    vj0_kernel<<<dim3(8, 8), 256>>>(W);

    for (int it = 0; it < 2; it++) {
        norm_kernel<<<1, 1024>>>();                // global L2 of vj
        c_kernel<<<dim3(32, 4), 128>>>(W);         // c = W_o @ vjn
        route_kernel<<<dim3(32, 8), 256>>>(u);     // b = u.c, softmax -> Wv
        g_kernel<<<dim3(32, 4), 256>>>(u);         // g = Wv @ u
        vj_kernel<<<dim3(32, 4), 256>>>(W);        // vj = g @ W_o
    }

    squash_kernel<<<1024, 64>>>(out);
}

// round 4
// speedup vs baseline: 1.3194x; 1.1213x over previous
#include <cuda_runtime.h>
#include <math.h>

#define BB   32
#define NIN  1024
#define DIN  512
#define NOUT 32
#define DCAP 64
#define FANOUT 2048   // NOUT*DCAP

// packed f32x2 helpers (FFMA2 path — only reachable via PTX)
#define FMA2(acc, a, b) asm("fma.rn.f32x2 %0, %1, %2, %0;" : "+l"(acc) : "l"(a), "l"(b))
#define DUP2(dst, f)    asm("mov.b64 %0, {%1, %1};" : "=l"(dst) : "r"(__float_as_uint(f)))
#define UNPK2(lo, hi, p) asm("mov.b64 {%0, %1}, %2;" : "=r"(lo), "=r"(hi) : "l"(p))

// ---- scratch (device globals; no allocation) ----
__device__ float d_g0p[8*BB*DIN];       // n-split partial sums for g0   (512 KB)
__device__ float d_g [BB*NOUT*DIN];     // g[b,o,k]                      (2 MB)
__device__ float d_c [BB*NOUT*DIN];     // c[b,o,k] = W_o @ vjn          (2 MB)
__device__ float d_vj[BB*NOUT*DCAP];    // vj[b,o,d]                     (256 KB)
__device__ float d_wv[BB*NOUT*NIN];     // softmax weights Wv[b,o,n]     (4 MB)
__device__ float d_sumsq[2];            // global sum-of-squares of vj per iteration

__device__ __forceinline__ void warp_red_add(float v, float* dst) {
#pragma unroll
    for (int off = 16; off > 0; off >>= 1) v += __shfl_xor_sync(~0u, v, off);
    if ((threadIdx.x & 31) == 0) atomicAdd(dst, v);
}

// ---------------------------------------------------------------------------
// partial[nt][b][k] = sum over 128 n of u[b,n,k]   (grid 32 x 4 x 8)
// block (0,0,0) also zeroes the sumsq slots for this graph replay
__global__ void g0_kernel(const float* __restrict__ u) {
    int b = blockIdx.x, kt = blockIdx.y, nt = blockIdx.z;
    if (b == 0 && kt == 0 && nt == 0 && threadIdx.x < 2) d_sumsq[threadIdx.x] = 0.f;
    int k = kt * 128 + threadIdx.x;
    const float* up = u + ((size_t)b * NIN + nt * 128) * DIN + k;
    float acc = 0.f;
#pragma unroll 8
    for (int n = 0; n < 128; n++) acc += up[(size_t)n * DIN];
    d_g0p[(nt * BB + b) * DIN + k] = acc;
}

// vj0[b,j] = sum_k g0[b,k] * W[k,j]; g0 = (1/32)*sum of 8 partials
// grid (8 jt x 8 bt of 4b), 256 threads; fuses sumsq into slot 0
__global__ void vj0_kernel(const float* __restrict__ W) {
    __shared__ float g0s[4 * DIN];     // 8 KB
    int jt = blockIdx.x, bt = blockIdx.y, tid = threadIdx.x;
    for (int i = 0; i < 8; i++) {
        int e = i * 256 + tid;
        int bl = e >> 9, k = e & 511;
        float s = 0.f;
#pragma unroll
        for (int nt = 0; nt < 8; nt++)
            s += d_g0p[(nt * BB + bt * 4 + bl) * DIN + k];
        g0s[e] = s * (1.0f / 32.0f);
    }
    __syncthreads();
    int j = jt * 256 + tid;
    float acc[4] = {};
#pragma unroll 8
    for (int k = 0; k < DIN; k++) {
        float w = W[(size_t)k * FANOUT + j];
#pragma unroll
        for (int q = 0; q < 4; q++) acc[q] += w * g0s[q * DIN + k];
    }
    float ss = 0.f;
#pragma unroll
    for (int q = 0; q < 4; q++) {
        d_vj[(bt * 4 + q) * FANOUT + j] = acc[q];
        ss += acc[q] * acc[q];
    }
    warp_red_add(ss, &d_sumsq[0]);
}

// ---------------------------------------------------------------------------
// c[b,o,k] = sum_d W[k, o*64+d] * vj[b,o,d] * inv_norm   (norm from d_sumsq[slot])
// grid (32 o x 4 kt x 2 bh of 16b), 128 threads (thread = k), packed over b
__global__ void c_kernel(const float* __restrict__ W, int slot) {
    __shared__ float vt[64 * 20];      // [d][bb(16)] pad 20
    __shared__ float ws[128 * 65];     // [kl][d] pad 65
    int o = blockIdx.x, kt = blockIdx.y, bh = blockIdx.z, tid = threadIdx.x;
    float inv = rsqrtf(fmaxf(d_sumsq[slot], 1e-12f));
    for (int i = 0; i < 8; i++) {
        int e = i * 128 + tid;
        int bb = e >> 6, d = e & 63;
        vt[d * 20 + bb] = d_vj[((bh * 16 + bb) * NOUT + o) * DCAP + d] * inv;
    }
    {
        const float* wp = W + (size_t)(kt * 128) * FANOUT + o * DCAP;
        for (int i = 0; i < 16; i++) {
            int e4 = i * 128 + tid;
            int kl = e4 >> 4, dq = e4 & 15;
            float4 v = *(const float4*)&wp[(size_t)kl * FANOUT + dq * 4];
            ws[kl * 65 + dq * 4 + 0] = v.x;
            ws[kl * 65 + dq * 4 + 1] = v.y;
            ws[kl * 65 + dq * 4 + 2] = v.z;
            ws[kl * 65 + dq * 4 + 3] = v.w;
        }
    }
    __syncthreads();
    unsigned long long acc[4][2] = {};
#pragma unroll 4
    for (int d = 0; d < 64; d++) {
        unsigned long long wd; DUP2(wd, ws[tid * 65 + d]);
#pragma unroll
        for (int bq = 0; bq < 4; bq++) {
            ulonglong2 vp = *(const ulonglong2*)&vt[d * 20 + bq * 4];
            FMA2(acc[bq][0], wd, vp.x);
            FMA2(acc[bq][1], wd, vp.y);
        }
    }
    int kg = kt * 128 + tid;
#pragma unroll
    for (int bq = 0; bq < 4; bq++)
#pragma unroll
        for (int p = 0; p < 2; p++) {
            unsigned lo, hi; UNPK2(lo, hi, acc[bq][p]);
            int bb = bh * 16 + bq * 4 + p * 2;
            d_c[(bb * NOUT + o) * DIN + kg]       = __uint_as_float(lo);
            d_c[((bb + 1) * NOUT + o) * DIN + kg] = __uint_as_float(hi);
        }
}

// ---------------------------------------------------------------------------
// fused: b[b,o,n] = sum_k u[b,n,k]*c[b,o,k]; softmax over o; write Wv[b,o,n]
// tile 128n x 32o, 256 threads, 4n x 4o per thread, packed over o
__global__ void route_kernel(const float* __restrict__ u) {
    __shared__ float sa[32 * 132];     // us_t [kk][n] during loop; ts [n][33] after
    __shared__ float sc[32 * 36];      // cs_t [kk][o]
    int b = blockIdx.x, n0 = blockIdx.y * 128, tid = threadIdx.x;
    int tn = tid & 31, to = tid >> 5;
    unsigned long long acc[4][2] = {};
    const float* ub = u + ((size_t)b * NIN + n0) * DIN;
    const float* cb = d_c + b * NOUT * DIN;
    for (int k0 = 0; k0 < DIN; k0 += 32) {
        __syncthreads();
#pragma unroll
        for (int i = 0; i < 16; i++) {
            int e = i * 256 + tid; int n = e >> 5, kk = e & 31;
            sa[kk * 132 + n] = ub[(size_t)n * DIN + k0 + kk];
        }
#pragma unroll
        for (int i = 0; i < 4; i++) {
            int e = i * 256 + tid; int o = e >> 5, kk = e & 31;
            sc[kk * 36 + o] = cb[o * DIN + k0 + kk];
        }
        __syncthreads();
#pragma unroll
        for (int kk = 0; kk < 32; kk++) {
            float4 av = *(const float4*)&sa[kk * 132 + tn * 4];
            ulonglong2 bp = *(const ulonglong2*)&sc[kk * 36 + to * 4];
            unsigned long long a0, a1, a2, a3;
            DUP2(a0, av.x); DUP2(a1, av.y); DUP2(a2, av.z); DUP2(a3, av.w);
            FMA2(acc[0][0], a0, bp.x); FMA2(acc[0][1], a0, bp.y);
            FMA2(acc[1][0], a1, bp.x); FMA2(acc[1][1], a1, bp.y);
            FMA2(acc[2][0], a2, bp.x); FMA2(acc[2][1], a2, bp.y);
            FMA2(acc[3][0], a3, bp.x); FMA2(acc[3][1], a3, bp.y);
        }
    }
    __syncthreads();
#pragma unroll
    for (int i = 0; i < 4; i++)
#pragma unroll
        for (int jp = 0; jp < 2; jp++) {
            unsigned lo, hi; UNPK2(lo, hi, acc[i][jp]);
            sa[(tn * 4 + i) * 33 + to * 4 + jp * 2 + 0] = __uint_as_float(lo);
            sa[(tn * 4 + i) * 33 + to * 4 + jp * 2 + 1] = __uint_as_float(hi);
        }
    __syncthreads();
    if (tid < 128) {   // softmax over 32 o for n=tid
        int n = tid;
        float m = -1e30f;
#pragma unroll
        for (int o = 0; o < 32; o++) m = fmaxf(m, sa[n * 33 + o]);
        float ex[32], s = 0.f;
#pragma unroll
        for (int o = 0; o < 32; o++) { ex[o] = expf(sa[n * 33 + o] - m); s += ex[o]; }
        float rs = 1.0f / s;
#pragma unroll
        for (int o = 0; o < 32; o++) sa[n * 33 + o] = ex[o] * rs;
    }
    __syncthreads();
#pragma unroll
    for (int i = 0; i < 16; i++) {
        int e = i * 256 + tid; int o = e >> 7, n = e & 127;
        d_wv[(b * NOUT + o) * NIN + n0 + n] = sa[n * 33 + o];
    }
}

// ---------------------------------------------------------------------------
// g[b,o,k] = sum_n Wv[b,o,n] * u[b,n,k]
// tile 32o x 64k, 128 threads, 4o x 4k per thread, packed over k
__global__ void g_kernel(const float* __restrict__ u) {
    __shared__ float su[32 * 68];      // [nn][k] pad 68
    __shared__ float sw[32 * 36];      // [nn][o] pad 36
    int b = blockIdx.x, k0 = blockIdx.y * 64, tid = threadIdx.x;
    int tk = tid & 15, to = tid >> 4;
    unsigned long long acc[4][2] = {}; // [o][k-pair]
    const float* ub = u + (size_t)b * NIN * DIN + k0;
    const float* wb = d_wv + b * NOUT * NIN;
    for (int n0 = 0; n0 < NIN; n0 += 32) {
        __syncthreads();
#pragma unroll
        for (int i = 0; i < 4; i++) {
            int e4 = i * 128 + tid; int nn = e4 >> 4, kq = e4 & 15;
            float4 v = *(const float4*)&ub[(size_t)(n0 + nn) * DIN + kq * 4];
            *(float4*)&su[nn * 68 + kq * 4] = v;
        }
#pragma unroll
        for (int i = 0; i < 8; i++) {
            int e = i * 128 + tid; int o = e >> 5, nn = e & 31;
            sw[nn * 36 + o] = wb[o * NIN + n0 + nn];
        }
        __syncthreads();
#pragma unroll
        for (int nn = 0; nn < 32; nn++) {
            ulonglong2 ap = *(const ulonglong2*)&su[nn * 68 + tk * 4];
            float4 wv = *(const float4*)&sw[nn * 36 + to * 4];
            unsigned long long w0, w1, w2, w3;
            DUP2(w0, wv.x); DUP2(w1, wv.y); DUP2(w2, wv.z); DUP2(w3, wv.w);
            FMA2(acc[0][0], w0, ap.x); FMA2(acc[0][1], w0, ap.y);
            FMA2(acc[1][0], w1, ap.x); FMA2(acc[1][1], w1, ap.y);
            FMA2(acc[2][0], w2, ap.x); FMA2(acc[2][1], w2, ap.y);
            FMA2(acc[3][0], w3, ap.x); FMA2(acc[3][1], w3, ap.y);
        }
    }
#pragma unroll
    for (int j = 0; j < 4; j++) {
        unsigned l0, h0, l1, h1;
        UNPK2(l0, h0, acc[j][0]);
        UNPK2(l1, h1, acc[j][1]);
        float4 v = make_float4(__uint_as_float(l0), __uint_as_float(h0),
                               __uint_as_float(l1), __uint_as_float(h1));
        *(float4*)&d_g[(b * NOUT + to * 4 + j) * DIN + k0 + tk * 4] = v;
    }
}

// vj[b,o,d] = sum_k g[b,o,k] * W[k, o*64+d], packed over d
// grid (32 o x 4 bh of 8b), 256 threads = 32 d2 x 8 b; sumsq fused when slot>=0
__global__ void vj_kernel(const float* __restrict__ W, int slot) {
    __shared__ float gs[8 * DIN];      // 16 KB
    int o = blockIdx.x, bh = blockIdx.y, tid = threadIdx.x;
    for (int i = 0; i < 16; i++) {
        int e = i * 256 + tid;
        int bl = e >> 9, k = e & 511;
        gs[e] = d_g[((bh * 8 + bl) * NOUT + o) * DIN + k];
        (void)bl; (void)k;
    }
    __syncthreads();
    int d2 = tid & 31, bg = tid >> 5;
    const unsigned long long* wp = (const unsigned long long*)(W + o * DCAP + d2 * 2);
    const float* gp = gs + bg * DIN;
    unsigned long long acc = 0ull;
#pragma unroll 8
    for (int k = 0; k < DIN; k++) {
        unsigned long long w = wp[(size_t)k * (FANOUT / 2)];
        unsigned long long gd; DUP2(gd, gp[k]);
        FMA2(acc, w, gd);
    }
    unsigned lo, hi; UNPK2(lo, hi, acc);
    float a0 = __uint_as_float(lo), a1 = __uint_as_float(hi);
    float2* outp = (float2*)&d_vj[((bh * 8 + bg) * NOUT + o) * DCAP + d2 * 2];
    *outp = make_float2(a0, a1);
    if (slot >= 0) warp_red_add(a0 * a0 + a1 * a1, &d_sumsq[slot]);
}

// ---------------------------------------------------------------------------
// squash(vj, axis=-1): s = sum_d v^2 + 1e-7; out = v * sqrt(s)/(0.5+s)
__global__ void squash_kernel(float* __restrict__ out) {
    int bo = blockIdx.x, d = threadIdx.x;
    float v = d_vj[bo * DCAP + d];
    float sq = v * v;
#pragma unroll
    for (int off = 16; off > 0; off >>= 1)
        sq += __shfl_xor_sync(0xffffffffu, sq, off);
    __shared__ float part[2];
    if ((d & 31) == 0) part[d >> 5] = sq;
    __syncthreads();
    float s = part[0] + part[1] + 1e-7f;
    float scale = sqrtf(s) / (0.5f + s);
    out[bo * DCAP + d] = v * scale;
}

// ---------------------------------------------------------------------------
extern "C" void kernel_launch(void* const* d_in, const int* in_sizes, int n_in,
                              void* d_out, int out_size) {
    const float* u = (const float*)d_in[0];   // [32,1024,512]
    const float* W = (const float*)d_in[1];   // [512,2048]
    float* out = (float*)d_out;               // [32,32,64]

    // iter 0: uniform softmax -> column mean of u, project through W
    g0_kernel<<<dim3(32, 4, 8), 128>>>(u);    // also zeroes d_sumsq
    vj0_kernel<<<dim3(8, 8), 256>>>(W);       // fuses sumsq -> slot 0

    // iteration 1
    c_kernel<<<dim3(32, 4, 2), 128>>>(W, 0);
    route_kernel<<<dim3(32, 8), 256>>>(u);
    g_kernel<<<dim3(32, 8), 128>>>(u);
    vj_kernel<<<dim3(32, 4), 256>>>(W, 1);    // fuses sumsq -> slot 1

    // iteration 2
    c_kernel<<<dim3(32, 4, 2), 128>>>(W, 1);
    route_kernel<<<dim3(32, 8), 256>>>(u);
    g_kernel<<<dim3(32, 8), 128>>>(u);
    vj_kernel<<<dim3(32, 4), 256>>>(W, -1);   // last vj: no norm needed

    squash_kernel<<<1024, 64>>>(out);
}